// round 7
// baseline (speedup 1.0000x reference)
#include <cuda_runtime.h>
#include <cstdint>

typedef unsigned long long u64;

#define B_    256
#define T_    512
#define NPAIR 128

// ---- device scratch (no allocations allowed) ------------------------------
__device__ __align__(16) float  g_seqA[(size_t)T_ * B_ * 64];   // 33.5 MB [t][b][64]
__device__ __align__(16) float4 g_pb0[(size_t)T_ * B_];         // 2 MB    [t*256+b]

// ---- packed f32x2 helpers -------------------------------------------------
__device__ __forceinline__ u64 pk2(float a, float b) {
    u64 r; asm("mov.b64 %0, {%1, %2};" : "=l"(r) : "f"(a), "f"(b)); return r;
}
__device__ __forceinline__ void unpk(u64 v, float& a, float& b) {
    asm("mov.b64 {%0, %1}, %2;" : "=f"(a), "=f"(b) : "l"(v));
}
__device__ __forceinline__ u64 ffma2(u64 a, u64 b, u64 c) {
    u64 d; asm("fma.rn.f32x2 %0, %1, %2, %3;" : "=l"(d) : "l"(a), "l"(b), "l"(c)); return d;
}
__device__ __forceinline__ u64 add2(u64 a, u64 b) {
    u64 d; asm("add.rn.f32x2 %0, %1, %2;" : "=l"(d) : "l"(a), "l"(b)); return d;
}
__device__ __forceinline__ float hsum1(u64 v) {
    float e, o; unpk(v, e, o); return e + o;
}
__device__ __forceinline__ float cmb(float x) {
    return x + __shfl_xor_sync(0xffffffffu, x, 1);
}

// ---- fast activations (MUFU ex2+rcp, ~1e-7 err) ---------------------------
#define L2E 1.4426950408889634f
__device__ __forceinline__ float ex2a(float x) {
    float r; asm("ex2.approx.ftz.f32 %0, %1;" : "=f"(r) : "f"(x)); return r;
}
__device__ __forceinline__ float rcpa(float x) {
    float r; asm("rcp.approx.ftz.f32 %0, %1;" : "=f"(r) : "f"(x)); return r;
}
__device__ __forceinline__ float sga(float x) { return rcpa(1.f + ex2a(-L2E * x)); }
__device__ __forceinline__ float tna(float x) {
    return fmaf(-2.f, rcpa(1.f + ex2a(2.f * L2E * x)), 1.f);
}

// ---- fused a0+a1+a2 pipeline, split-K, 512 threads ------------------------
// 128 blocks (one batch pair). Thread = (gate g, K-half k):
//   lane = 2*(g%16)+k in warp (g>>... warp = g/16). Halves combined via
//   shfl_xor(1). Half-1 iterates chunks staggered (j^4) for conflict-free
//   paired h loads. Step s: a0@t=s, a1@t=s-1, a2@t=s-2 (R6 skew).
// Weights: whh_a0/whh_a1 halves in regs (32 u64); wih_a1/wih_a2/whh_a2 in
// smem transposed [chunk16B][gate].
//
// dynamic smem layout (bytes):
//   [0,      65536)  wT1 = wih_a1  as ulonglong2[16][256]
//   [65536, 131072)  wT2 = wih_a2
//   [131072,196608)  wT3 = whh_a2
//   [196608,200704)  xs  = float[2][512]
//   [200704,206848)  gsm = float2[3][256]
//   [206848,208384)  hs  = float[3][2][64]
#define SMEM_FUSE_BYTES 208384

__global__ __launch_bounds__(512, 1) void fuseA(
    const float* __restrict__ x,
    const float* __restrict__ wih_a0, const float* __restrict__ whh_a0,
    const float* __restrict__ bih_a0, const float* __restrict__ bhh_a0,
    const float* __restrict__ wih_a1, const float* __restrict__ whh_a1,
    const float* __restrict__ bih_a1, const float* __restrict__ bhh_a1,
    const float* __restrict__ wih_a2, const float* __restrict__ whh_a2,
    const float* __restrict__ bih_a2, const float* __restrict__ bhh_a2)
{
    extern __shared__ __align__(16) char smem[];
    ulonglong2* wT1 = reinterpret_cast<ulonglong2*>(smem);
    ulonglong2* wT2 = reinterpret_cast<ulonglong2*>(smem + 65536);
    ulonglong2* wT3 = reinterpret_cast<ulonglong2*>(smem + 131072);
    float*  xs  = reinterpret_cast<float*>(smem + 196608);   // [2][512]
    float2* gsm = reinterpret_cast<float2*>(smem + 200704);  // [3][256]
    float*  hs  = reinterpret_cast<float*>(smem + 206848);   // [3][2][64]

    const int tid  = threadIdx.x;
    const int lane = tid & 31;
    const int g    = (tid >> 5) * 16 + (lane >> 1);  // gate 0..255
    const int k    = lane & 1;                       // K-half
    const int pair = blockIdx.x;

    // staggered chunk order: k=0 -> j; k=1 -> 8+(j^4)  (disjoint banks)
    int cidx[8];
#pragma unroll
    for (int j = 0; j < 8; ++j) cidx[j] = (k << 3) + (j ^ (k << 2));

    // register weight halves for whh_a0 / whh_a1 (chunk c -> u64 2c, 2c+1)
    u64 wr0[16], wr1[16];
    {
        const u64* p0 = reinterpret_cast<const u64*>(whh_a0) + (size_t)g * 32;
        const u64* p1 = reinterpret_cast<const u64*>(whh_a1) + (size_t)g * 32;
#pragma unroll
        for (int j = 0; j < 8; ++j) {
            int c2 = cidx[j] * 2;
            wr0[2 * j]     = __ldg(p0 + c2);
            wr0[2 * j + 1] = __ldg(p0 + c2 + 1);
            wr1[2 * j]     = __ldg(p1 + c2);
            wr1[2 * j + 1] = __ldg(p1 + c2 + 1);
        }
    }
    // stage smem sets transposed [chunk][gate]
    {
        const ulonglong2* s1 = reinterpret_cast<const ulonglong2*>(wih_a1);
        const ulonglong2* s2 = reinterpret_cast<const ulonglong2*>(wih_a2);
        const ulonglong2* s3 = reinterpret_cast<const ulonglong2*>(whh_a2);
#pragma unroll
        for (int i = 0; i < 8; ++i) {
            int idx = i * 512 + tid;
            int ch = idx >> 8, gt = idx & 255;
            wT1[idx] = __ldg(s1 + (size_t)gt * 16 + ch);
            wT2[idx] = __ldg(s2 + (size_t)gt * 16 + ch);
            wT3[idx] = __ldg(s3 + (size_t)gt * 16 + ch);
        }
    }
    // x staging
    xs[tid]       = x[(size_t)(pair * 2) * T_ + tid];
    xs[512 + tid] = x[(size_t)(pair * 2 + 1) * T_ + tid];
    if (tid < 384) hs[tid] = 0.f;

    const float bias0 = __ldg(bih_a0 + g) + __ldg(bhh_a0 + g);
    const float bias1 = __ldg(bih_a1 + g) + __ldg(bhh_a1 + g);
    const float bias2 = __ldg(bih_a2 + g) + __ldg(bhh_a2 + g);
    const float wx0   = __ldg(wih_a0 + g);

    const bool istanh = (g >= 128 && g < 192);
    const float ca = istanh ? 2.f * L2E : -L2E;
    const float aa = istanh ? 1.f : 0.f;
    const float bm = istanh ? -2.f : 1.f;

    // phase-2 assignment: threads 0..383, one layer each
    const int pl  = tid >> 7;            // layer 0..2 (for tid<384)
    const int pu  = tid & 63;
    const int pnb = (tid >> 6) & 1;
    float c = 0.f;
    __syncthreads();

#pragma unroll 1
    for (int s = 0; s < T_ + 2; ++s) {
        const bool L0 = (s < T_);
        const bool L1 = (s >= 1) & (s < T_ + 1);
        const bool L2 = (s >= 2);

        float v0a = 0.f, v0b = 0.f, p1a = 0.f, p1b = 0.f;
        float h1a = 0.f, h1b = 0.f, p2a = 0.f, p2b = 0.f;
        float h2a = 0.f, h2b = 0.f;

        // ---- group A: whh_a0 (regs) + wih_a1 (smem) over h0 ----
        if (L0 | L1) {
            const ulonglong2* q0p = reinterpret_cast<const ulonglong2*>(hs);
            const ulonglong2* q1p = reinterpret_cast<const ulonglong2*>(hs + 64);
            u64 A = 0, Bv = 0, I = 0, J = 0;
#pragma unroll
            for (int j = 0; j < 8; ++j) {
                int ct = cidx[j];
                ulonglong2 q0 = q0p[ct], q1 = q1p[ct];
                ulonglong2 wv = wT1[(ct << 8) + g];
                A  = ffma2(wr0[2 * j], q0.x, A);  A  = ffma2(wr0[2 * j + 1], q0.y, A);
                Bv = ffma2(wr0[2 * j], q1.x, Bv); Bv = ffma2(wr0[2 * j + 1], q1.y, Bv);
                I  = ffma2(wv.x, q0.x, I);        I  = ffma2(wv.y, q0.y, I);
                J  = ffma2(wv.x, q1.x, J);        J  = ffma2(wv.y, q1.y, J);
            }
            v0a = hsum1(A); v0b = hsum1(Bv); p1a = hsum1(I); p1b = hsum1(J);
        }
        // ---- group B: whh_a1 (regs) + wih_a2 (smem) over h1 ----
        if (L1 | L2) {
            const ulonglong2* q0p = reinterpret_cast<const ulonglong2*>(hs + 128);
            const ulonglong2* q1p = reinterpret_cast<const ulonglong2*>(hs + 192);
            u64 A = 0, Bv = 0, I = 0, J = 0;
#pragma unroll
            for (int j = 0; j < 8; ++j) {
                int ct = cidx[j];
                ulonglong2 q0 = q0p[ct], q1 = q1p[ct];
                ulonglong2 wv = wT2[(ct << 8) + g];
                A  = ffma2(wr1[2 * j], q0.x, A);  A  = ffma2(wr1[2 * j + 1], q0.y, A);
                Bv = ffma2(wr1[2 * j], q1.x, Bv); Bv = ffma2(wr1[2 * j + 1], q1.y, Bv);
                I  = ffma2(wv.x, q0.x, I);        I  = ffma2(wv.y, q0.y, I);
                J  = ffma2(wv.x, q1.x, J);        J  = ffma2(wv.y, q1.y, J);
            }
            h1a = hsum1(A); h1b = hsum1(Bv); p2a = hsum1(I); p2b = hsum1(J);
        }
        // ---- group C: whh_a2 (smem) over h2 ----
        if (L2) {
            const ulonglong2* q0p = reinterpret_cast<const ulonglong2*>(hs + 256);
            const ulonglong2* q1p = reinterpret_cast<const ulonglong2*>(hs + 320);
            u64 A = 0, Bv = 0;
#pragma unroll
            for (int j = 0; j < 8; ++j) {
                int ct = cidx[j];
                ulonglong2 q0 = q0p[ct], q1 = q1p[ct];
                ulonglong2 wv = wT3[(ct << 8) + g];
                A  = ffma2(wv.x, q0.x, A);  A  = ffma2(wv.y, q0.y, A);
                Bv = ffma2(wv.x, q1.x, Bv); Bv = ffma2(wv.y, q1.y, Bv);
            }
            h2a = hsum1(A); h2b = hsum1(Bv);
        }

        // ---- combine K-halves across lane pairs (full warp) ----
        v0a = cmb(v0a); v0b = cmb(v0b); p1a = cmb(p1a); p1b = cmb(p1b);
        h1a = cmb(h1a); h1b = cmb(h1b); p2a = cmb(p2a); p2b = cmb(p2b);
        h2a = cmb(h2a); h2b = cmb(h2b);

        if (k == 0) {
            if (L0) {
                float va = v0a + fmaf(wx0, xs[s], bias0);
                float vb = v0b + fmaf(wx0, xs[512 + s], bias0);
                gsm[g] = make_float2(fmaf(bm, rcpa(1.f + ex2a(ca * va)), aa),
                                     fmaf(bm, rcpa(1.f + ex2a(ca * vb)), aa));
            }
            if (L1) {
                float va = h1a + p1a + bias1;
                float vb = h1b + p1b + bias1;
                gsm[256 + g] = make_float2(fmaf(bm, rcpa(1.f + ex2a(ca * va)), aa),
                                           fmaf(bm, rcpa(1.f + ex2a(ca * vb)), aa));
            }
            if (L2) {
                float va = h2a + p2a + bias2;
                float vb = h2b + p2b + bias2;
                gsm[512 + g] = make_float2(fmaf(bm, rcpa(1.f + ex2a(ca * va)), aa),
                                           fmaf(bm, rcpa(1.f + ex2a(ca * vb)), aa));
            }
        }
        __syncthreads();

        // ---- phase 2: per-layer c/h update (384 threads, 1 layer each) ----
        if (tid < 384) {
            const bool go = (pl == 0) ? L0 : (pl == 1) ? L1 : L2;
            if (go) {
                const float2* gb = gsm + pl * 256;
                float2 gi = gb[pu], gf = gb[pu + 64];
                float2 gg = gb[pu + 128], go4 = gb[pu + 192];
                float iv = pnb ? gi.y : gi.x, fv = pnb ? gf.y : gf.x;
                float gv = pnb ? gg.y : gg.x, ov = pnb ? go4.y : go4.x;
                c = fmaf(fv, c, iv * gv);
                float h = ov * tna(c);
                hs[pl * 128 + pnb * 64 + pu] = h;
                if (pl == 2)
                    g_seqA[((size_t)(s - 2) * B_ + pair * 2 + pnb) * 64 + pu] = h;
            }
        }
        __syncthreads();
    }
}

// ---------------------------------------------------------------------------
// b0 pre-gates: g_pb0[t*256+b] = bias_b0 + W_ih_b0[4,64] . seqA[t][b]
// ---------------------------------------------------------------------------
__global__ __launch_bounds__(256, 1) void preb0(
    const float* __restrict__ w_ih, const float* __restrict__ b_ih,
    const float* __restrict__ b_hh)
{
    __shared__ u64 wsm[128];
    __shared__ float bsm[4];
    const int tid = threadIdx.x;
    if (tid < 128) wsm[tid] = __ldg(reinterpret_cast<const u64*>(w_ih) + tid);
    if (tid < 4) bsm[tid] = __ldg(b_ih + tid) + __ldg(b_hh + tid);
    __syncthreads();

    const size_t slot = (size_t)blockIdx.x * 256 + tid;  // = t*256 + b
    const u64* xp = reinterpret_cast<const u64*>(g_seqA) + slot * 32;
    u64 acc[4] = {0ull, 0ull, 0ull, 0ull};
#pragma unroll 8
    for (int j = 0; j < 32; ++j) {
        u64 xv = __ldg(xp + j);
#pragma unroll
        for (int gg = 0; gg < 4; ++gg)
            acc[gg] = ffma2(wsm[gg * 32 + j], xv, acc[gg]);
    }
    float r[4];
#pragma unroll
    for (int gg = 0; gg < 4; ++gg) {
        float e, o; unpk(acc[gg], e, o);
        r[gg] = e + o + bsm[gg];
    }
    g_pb0[slot] = make_float4(r[0], r[1], r[2], r[3]);
}

// ---------------------------------------------------------------------------
// b0,b1,b2 scalar recurrences, layer-pipelined. 8 blocks x 32 threads.
// ---------------------------------------------------------------------------
__device__ __forceinline__ void step1(float4 pre, float4 whh, float& c, float& h) {
    float iv = sga(fmaf(whh.x, h, pre.x));
    float fv = sga(fmaf(whh.y, h, pre.y));
    float gv = tna(fmaf(whh.z, h, pre.z));
    float ov = sga(fmaf(whh.w, h, pre.w));
    c = fmaf(fv, c, iv * gv);
    h = ov * tna(c);
}

__global__ __launch_bounds__(32, 1) void b012(
    const float* __restrict__ whh0,
    const float* __restrict__ wih1, const float* __restrict__ whh1,
    const float* __restrict__ bih1, const float* __restrict__ bhh1,
    const float* __restrict__ wih2, const float* __restrict__ whh2,
    const float* __restrict__ bih2, const float* __restrict__ bhh2,
    float* __restrict__ out)
{
    const int b = blockIdx.x * 32 + threadIdx.x;
    float4 W0 = make_float4(whh0[0], whh0[1], whh0[2], whh0[3]);
    float4 I1 = make_float4(wih1[0], wih1[1], wih1[2], wih1[3]);
    float4 H1 = make_float4(whh1[0], whh1[1], whh1[2], whh1[3]);
    float4 B1 = make_float4(bih1[0] + bhh1[0], bih1[1] + bhh1[1],
                            bih1[2] + bhh1[2], bih1[3] + bhh1[3]);
    float4 I2 = make_float4(wih2[0], wih2[1], wih2[2], wih2[3]);
    float4 H2 = make_float4(whh2[0], whh2[1], whh2[2], whh2[3]);
    float4 B2 = make_float4(bih2[0] + bhh2[0], bih2[1] + bhh2[1],
                            bih2[2] + bhh2[2], bih2[3] + bhh2[3]);

    float c0 = 0.f, h0 = 0.f, c1 = 0.f, h1 = 0.f, c2 = 0.f, h2v = 0.f;
    float4 p0 = g_pb0[b];
    float4 p1 = g_pb0[256 + b];

    for (int tt = 0; tt < T_ + 2; ++tt) {
        float4 pn = (tt + 2 < T_) ? g_pb0[(size_t)(tt + 2) * 256 + b]
                                  : make_float4(0.f, 0.f, 0.f, 0.f);
        float in0 = h0, in1 = h1;
        if (tt < T_) step1(p0, W0, c0, h0);
        if (tt >= 1 && tt < T_ + 1) {
            float4 pre = make_float4(fmaf(I1.x, in0, B1.x), fmaf(I1.y, in0, B1.y),
                                     fmaf(I1.z, in0, B1.z), fmaf(I1.w, in0, B1.w));
            step1(pre, H1, c1, h1);
        }
        if (tt >= 2) {
            float4 pre = make_float4(fmaf(I2.x, in1, B2.x), fmaf(I2.y, in1, B2.y),
                                     fmaf(I2.z, in1, B2.z), fmaf(I2.w, in1, B2.w));
            step1(pre, H2, c2, h2v);
            out[(size_t)b * T_ + (tt - 2)] = h2v;
        }
        p0 = p1; p1 = pn;
    }
}

// ---------------------------------------------------------------------------
extern "C" void kernel_launch(void* const* d_in, const int* in_sizes, int n_in,
                              void* d_out, int out_size)
{
    const float* x = (const float*)d_in[0];
    const float *wih_a0 = (const float*)d_in[1],  *whh_a0 = (const float*)d_in[2];
    const float *bih_a0 = (const float*)d_in[3],  *bhh_a0 = (const float*)d_in[4];
    const float *wih_a1 = (const float*)d_in[5],  *whh_a1 = (const float*)d_in[6];
    const float *bih_a1 = (const float*)d_in[7],  *bhh_a1 = (const float*)d_in[8];
    const float *wih_a2 = (const float*)d_in[9],  *whh_a2 = (const float*)d_in[10];
    const float *bih_a2 = (const float*)d_in[11], *bhh_a2 = (const float*)d_in[12];
    const float *wih_b0 = (const float*)d_in[13], *whh_b0 = (const float*)d_in[14];
    const float *bih_b0 = (const float*)d_in[15], *bhh_b0 = (const float*)d_in[16];
    const float *wih_b1 = (const float*)d_in[17], *whh_b1 = (const float*)d_in[18];
    const float *bih_b1 = (const float*)d_in[19], *bhh_b1 = (const float*)d_in[20];
    const float *wih_b2 = (const float*)d_in[21], *whh_b2 = (const float*)d_in[22];
    const float *bih_b2 = (const float*)d_in[23], *bhh_b2 = (const float*)d_in[24];
    float* out = (float*)d_out;

    cudaFuncSetAttribute(fuseA, cudaFuncAttributeMaxDynamicSharedMemorySize,
                         SMEM_FUSE_BYTES);

    // fused a0+a1+a2 pipeline -> g_seqA
    fuseA<<<NPAIR, 512, SMEM_FUSE_BYTES>>>(
        x,
        wih_a0, whh_a0, bih_a0, bhh_a0,
        wih_a1, whh_a1, bih_a1, bhh_a1,
        wih_a2, whh_a2, bih_a2, bhh_a2);
    // b0 pre-gates from g_seqA
    preb0<<<512, 256>>>(wih_b0, bih_b0, bhh_b0);
    // b0/b1/b2 fused scalar recurrences -> out
    b012<<<8, 32>>>(whh_b0, wih_b1, whh_b1, bih_b1, bhh_b1,
                    wih_b2, whh_b2, bih_b2, bhh_b2, out);
}

// round 8
// speedup vs baseline: 1.4631x; 1.4631x over previous
#include <cuda_runtime.h>
#include <cstdint>

typedef unsigned long long u64;

#define B_    256
#define T_    512
#define NPAIR 128

// ---- device scratch (no allocations allowed) ------------------------------
__device__ __align__(16) float  g_seqA[(size_t)T_ * B_ * 64];   // 33.5 MB [t][b][64]
__device__ __align__(16) float4 g_pb0[(size_t)T_ * B_];         // 2 MB    [t*256+b]

// ---- packed f32x2 helpers -------------------------------------------------
__device__ __forceinline__ u64 pk2(float a, float b) {
    u64 r; asm("mov.b64 %0, {%1, %2};" : "=l"(r) : "f"(a), "f"(b)); return r;
}
__device__ __forceinline__ void unpk(u64 v, float& a, float& b) {
    asm("mov.b64 {%0, %1}, %2;" : "=f"(a), "=f"(b) : "l"(v));
}
__device__ __forceinline__ u64 ffma2(u64 a, u64 b, u64 c) {
    u64 d; asm("fma.rn.f32x2 %0, %1, %2, %3;" : "=l"(d) : "l"(a), "l"(b), "l"(c)); return d;
}
__device__ __forceinline__ u64 add2(u64 a, u64 b) {
    u64 d; asm("add.rn.f32x2 %0, %1, %2;" : "=l"(d) : "l"(a), "l"(b)); return d;
}
__device__ __forceinline__ float hsum2(u64 x, u64 y) {
    u64 s = add2(x, y);
    float e, o; unpk(s, e, o);
    return e + o;
}

// ---- fast activations (MUFU ex2+rcp, ~1e-7 err) ---------------------------
#define L2E 1.4426950408889634f
__device__ __forceinline__ float ex2a(float x) {
    float r; asm("ex2.approx.ftz.f32 %0, %1;" : "=f"(r) : "f"(x)); return r;
}
__device__ __forceinline__ float rcpa(float x) {
    float r; asm("rcp.approx.ftz.f32 %0, %1;" : "=f"(r) : "f"(x)); return r;
}
__device__ __forceinline__ float sga(float x) { return rcpa(1.f + ex2a(-L2E * x)); }
__device__ __forceinline__ float tna(float x) {
    return fmaf(-2.f, rcpa(1.f + ex2a(2.f * L2E * x)), 1.f);
}

// ---- fused a0+a1+a2 pipeline kernel (3 reg sets + 2 smem sets) -------------
// 128 blocks (one batch pair), 256 threads (one gate each).
// Step s: a0 gates @t=s, a1 gates @t=s-1, a2 gates @t=s-2.
// Registers: whh_a0 (wr0), wih_a1 (wr1), whh_a1 (wr2) dim-packed, 32 u64 each.
// Smem (transposed [chunk16B][gate]): wih_a2 (wT2), whh_a2 (wT3).
//
// dynamic smem layout (bytes):
//   [0,      65536)   wT2 = wih_a2  as ulonglong2[16][256]
//   [65536, 131072)   wT3 = whh_a2
//   [131072,135168)   xs  = float[2][512]
//   [135168,141312)   gsm = float2[3][256]
//   [141312,142848)   hs  = float[3][2][64]
#define SMEM_FUSE_BYTES 142848

__global__ __launch_bounds__(256, 1) void fuseA(
    const float* __restrict__ x,
    const float* __restrict__ wih_a0, const float* __restrict__ whh_a0,
    const float* __restrict__ bih_a0, const float* __restrict__ bhh_a0,
    const float* __restrict__ wih_a1, const float* __restrict__ whh_a1,
    const float* __restrict__ bih_a1, const float* __restrict__ bhh_a1,
    const float* __restrict__ wih_a2, const float* __restrict__ whh_a2,
    const float* __restrict__ bih_a2, const float* __restrict__ bhh_a2)
{
    extern __shared__ __align__(16) char smem[];
    ulonglong2* wT2 = reinterpret_cast<ulonglong2*>(smem);
    ulonglong2* wT3 = reinterpret_cast<ulonglong2*>(smem + 65536);
    float*  xs  = reinterpret_cast<float*>(smem + 131072);   // [2][512]
    float2* gsm = reinterpret_cast<float2*>(smem + 135168);  // [3][256]
    float*  hs  = reinterpret_cast<float*>(smem + 141312);   // [3][2][64]

    const int g    = threadIdx.x;
    const int pair = blockIdx.x;

    // ---- register weight sets (dim-packed u64 rows: 32 u64 each) ----
    u64 wr0[32], wr1[32], wr2[32];
    {
        const u64* p0 = reinterpret_cast<const u64*>(whh_a0) + (size_t)g * 32;
        const u64* p1 = reinterpret_cast<const u64*>(wih_a1) + (size_t)g * 32;
        const u64* p2 = reinterpret_cast<const u64*>(whh_a1) + (size_t)g * 32;
#pragma unroll
        for (int j = 0; j < 32; ++j) {
            wr0[j] = __ldg(p0 + j);
            wr1[j] = __ldg(p1 + j);
            wr2[j] = __ldg(p2 + j);
        }
    }
    // ---- smem transposed weight sets: wT[i][g] = 16B chunk i of row g ----
    {
        const ulonglong2* p2 = reinterpret_cast<const ulonglong2*>(wih_a2) + (size_t)g * 16;
        const ulonglong2* p3 = reinterpret_cast<const ulonglong2*>(whh_a2) + (size_t)g * 16;
#pragma unroll
        for (int i = 0; i < 16; ++i) {
            wT2[i * 256 + g] = __ldg(p2 + i);
            wT3[i * 256 + g] = __ldg(p3 + i);
        }
    }
    // ---- x staging ----
#pragma unroll
    for (int k = 0; k < 4; ++k) {
        int i = g + 256 * k, bl = i >> 9, t = i & 511;
        xs[bl * 512 + t] = x[(size_t)(pair * 2 + bl) * T_ + t];
    }
    // ---- h init ----
    if (g < 128) {
#pragma unroll
        for (int L = 0; L < 3; ++L) hs[L * 128 + g] = 0.f;
    }

    const float bias0 = __ldg(bih_a0 + g) + __ldg(bhh_a0 + g);
    const float bias1 = __ldg(bih_a1 + g) + __ldg(bhh_a1 + g);
    const float bias2 = __ldg(bih_a2 + g) + __ldg(bhh_a2 + g);
    const float wx0   = __ldg(wih_a0 + g);

    const bool istanh = (g >= 128 && g < 192);
    const float ca = istanh ? 2.f * L2E : -L2E;
    const float aa = istanh ? 1.f : 0.f;
    const float bm = istanh ? -2.f : 1.f;

    float c0 = 0.f, c1 = 0.f, c2 = 0.f;
    __syncthreads();

#pragma unroll 1
    for (int s = 0; s < T_ + 2; ++s) {
        const bool L0 = (s < T_);
        const bool L1 = (s >= 1) & (s < T_ + 1);
        const bool L2 = (s >= 2);

        float v0a = 0.f, v0b = 0.f, p1a = 0.f, p1b = 0.f;
        float h1a = 0.f, h1b = 0.f, p2a = 0.f, p2b = 0.f;
        float h2a = 0.f, h2b = 0.f;

        // ---- group A: whh_a0 (wr0) + wih_a1 (wr1) over h0 -- all regs ----
        if (L0 | L1) {
            const ulonglong2* q0p = reinterpret_cast<const ulonglong2*>(hs + 0);
            const ulonglong2* q1p = reinterpret_cast<const ulonglong2*>(hs + 64);
            u64 ax = 0, bx = 0, ix = 0, jx = 0;
#pragma unroll
            for (int i = 0; i < 16; ++i) {
                ulonglong2 q0 = q0p[i], q1 = q1p[i];
                ax = ffma2(wr0[2 * i], q0.x, ax); ax = ffma2(wr0[2 * i + 1], q0.y, ax);
                bx = ffma2(wr0[2 * i], q1.x, bx); bx = ffma2(wr0[2 * i + 1], q1.y, bx);
                ix = ffma2(wr1[2 * i], q0.x, ix); ix = ffma2(wr1[2 * i + 1], q0.y, ix);
                jx = ffma2(wr1[2 * i], q1.x, jx); jx = ffma2(wr1[2 * i + 1], q1.y, jx);
            }
            float e, o;
            unpk(ax, e, o); v0a = e + o;
            unpk(bx, e, o); v0b = e + o;
            unpk(ix, e, o); p1a = e + o;
            unpk(jx, e, o); p1b = e + o;
        }
        // ---- group B: whh_a1 (wr2 regs) + wih_a2 (wT2 smem) over h1 ----
        if (L1 | L2) {
            const ulonglong2* q0p = reinterpret_cast<const ulonglong2*>(hs + 128);
            const ulonglong2* q1p = reinterpret_cast<const ulonglong2*>(hs + 192);
            u64 ax = 0, bx = 0, ix = 0, jx = 0;
#pragma unroll
            for (int i = 0; i < 16; ++i) {
                ulonglong2 q0 = q0p[i], q1 = q1p[i];
                ulonglong2 wv = wT2[i * 256 + g];
                ax = ffma2(wr2[2 * i], q0.x, ax); ax = ffma2(wr2[2 * i + 1], q0.y, ax);
                bx = ffma2(wr2[2 * i], q1.x, bx); bx = ffma2(wr2[2 * i + 1], q1.y, bx);
                ix = ffma2(wv.x, q0.x, ix);       ix = ffma2(wv.y, q0.y, ix);
                jx = ffma2(wv.x, q1.x, jx);       jx = ffma2(wv.y, q1.y, jx);
            }
            float e, o;
            unpk(ax, e, o); h1a = e + o;
            unpk(bx, e, o); h1b = e + o;
            unpk(ix, e, o); p2a = e + o;
            unpk(jx, e, o); p2b = e + o;
        }
        // ---- group C: whh_a2 (wT3 smem) over h2 ----
        if (L2) {
            const ulonglong2* q0p = reinterpret_cast<const ulonglong2*>(hs + 256);
            const ulonglong2* q1p = reinterpret_cast<const ulonglong2*>(hs + 320);
            u64 ax = 0, bx = 0;
#pragma unroll
            for (int i = 0; i < 16; ++i) {
                ulonglong2 q0 = q0p[i], q1 = q1p[i];
                ulonglong2 wv = wT3[i * 256 + g];
                ax = ffma2(wv.x, q0.x, ax); ax = ffma2(wv.y, q0.y, ax);
                bx = ffma2(wv.x, q1.x, bx); bx = ffma2(wv.y, q1.y, bx);
            }
            float e, o;
            unpk(ax, e, o); h2a = e + o;
            unpk(bx, e, o); h2b = e + o;
        }

        // ---- activations -> gsm ----
        if (L0) {
            float va = v0a + fmaf(wx0, xs[s], bias0);
            float vb = v0b + fmaf(wx0, xs[512 + s], bias0);
            gsm[g] = make_float2(fmaf(bm, rcpa(1.f + ex2a(ca * va)), aa),
                                 fmaf(bm, rcpa(1.f + ex2a(ca * vb)), aa));
        }
        if (L1) {
            float va = h1a + p1a + bias1;
            float vb = h1b + p1b + bias1;
            gsm[256 + g] = make_float2(fmaf(bm, rcpa(1.f + ex2a(ca * va)), aa),
                                       fmaf(bm, rcpa(1.f + ex2a(ca * vb)), aa));
        }
        if (L2) {
            float va = h2a + p2a + bias2;
            float vb = h2b + p2b + bias2;
            gsm[512 + g] = make_float2(fmaf(bm, rcpa(1.f + ex2a(ca * va)), aa),
                                       fmaf(bm, rcpa(1.f + ex2a(ca * vb)), aa));
        }
        __syncthreads();

        // ---- phase 2: c/h update (threads 0..127) ----
        if (g < 128) {
            const int u = g & 63, nb = g >> 6;
            if (L0) {
                float2 gi = gsm[u], gf = gsm[u + 64], gg = gsm[u + 128], go = gsm[u + 192];
                float iv = nb ? gi.y : gi.x, fv = nb ? gf.y : gf.x;
                float gv = nb ? gg.y : gg.x, ov = nb ? go.y : go.x;
                c0 = fmaf(fv, c0, iv * gv);
                hs[nb * 64 + u] = ov * tna(c0);
            }
            if (L1) {
                float2 gi = gsm[256 + u], gf = gsm[320 + u], gg = gsm[384 + u], go = gsm[448 + u];
                float iv = nb ? gi.y : gi.x, fv = nb ? gf.y : gf.x;
                float gv = nb ? gg.y : gg.x, ov = nb ? go.y : go.x;
                c1 = fmaf(fv, c1, iv * gv);
                hs[128 + nb * 64 + u] = ov * tna(c1);
            }
            if (L2) {
                float2 gi = gsm[512 + u], gf = gsm[576 + u], gg = gsm[640 + u], go = gsm[704 + u];
                float iv = nb ? gi.y : gi.x, fv = nb ? gf.y : gf.x;
                float gv = nb ? gg.y : gg.x, ov = nb ? go.y : go.x;
                c2 = fmaf(fv, c2, iv * gv);
                float h = ov * tna(c2);
                hs[256 + nb * 64 + u] = h;
                g_seqA[((size_t)(s - 2) * B_ + pair * 2 + nb) * 64 + u] = h;
            }
        }
        __syncthreads();
    }
}

// ---------------------------------------------------------------------------
// b0 pre-gates: g_pb0[t*256+b] = bias_b0 + W_ih_b0[4,64] . seqA[t][b]
// ---------------------------------------------------------------------------
__global__ __launch_bounds__(256, 1) void preb0(
    const float* __restrict__ w_ih, const float* __restrict__ b_ih,
    const float* __restrict__ b_hh)
{
    __shared__ u64 wsm[128];
    __shared__ float bsm[4];
    const int tid = threadIdx.x;
    if (tid < 128) wsm[tid] = __ldg(reinterpret_cast<const u64*>(w_ih) + tid);
    if (tid < 4) bsm[tid] = __ldg(b_ih + tid) + __ldg(b_hh + tid);
    __syncthreads();

    const size_t slot = (size_t)blockIdx.x * 256 + tid;  // = t*256 + b
    const u64* xp = reinterpret_cast<const u64*>(g_seqA) + slot * 32;
    u64 acc[4] = {0ull, 0ull, 0ull, 0ull};
#pragma unroll 8
    for (int j = 0; j < 32; ++j) {
        u64 xv = __ldg(xp + j);
#pragma unroll
        for (int gg = 0; gg < 4; ++gg)
            acc[gg] = ffma2(wsm[gg * 32 + j], xv, acc[gg]);
    }
    float r[4];
#pragma unroll
    for (int gg = 0; gg < 4; ++gg) {
        float e, o; unpk(acc[gg], e, o);
        r[gg] = e + o + bsm[gg];
    }
    g_pb0[slot] = make_float4(r[0], r[1], r[2], r[3]);
}

// ---------------------------------------------------------------------------
// b0,b1,b2 scalar recurrences, layer-pipelined. 8 blocks x 32 threads.
// ---------------------------------------------------------------------------
__device__ __forceinline__ void step1(float4 pre, float4 whh, float& c, float& h) {
    float iv = sga(fmaf(whh.x, h, pre.x));
    float fv = sga(fmaf(whh.y, h, pre.y));
    float gv = tna(fmaf(whh.z, h, pre.z));
    float ov = sga(fmaf(whh.w, h, pre.w));
    c = fmaf(fv, c, iv * gv);
    h = ov * tna(c);
}

__global__ __launch_bounds__(32, 1) void b012(
    const float* __restrict__ whh0,
    const float* __restrict__ wih1, const float* __restrict__ whh1,
    const float* __restrict__ bih1, const float* __restrict__ bhh1,
    const float* __restrict__ wih2, const float* __restrict__ whh2,
    const float* __restrict__ bih2, const float* __restrict__ bhh2,
    float* __restrict__ out)
{
    const int b = blockIdx.x * 32 + threadIdx.x;
    float4 W0 = make_float4(whh0[0], whh0[1], whh0[2], whh0[3]);
    float4 I1 = make_float4(wih1[0], wih1[1], wih1[2], wih1[3]);
    float4 H1 = make_float4(whh1[0], whh1[1], whh1[2], whh1[3]);
    float4 B1 = make_float4(bih1[0] + bhh1[0], bih1[1] + bhh1[1],
                            bih1[2] + bhh1[2], bih1[3] + bhh1[3]);
    float4 I2 = make_float4(wih2[0], wih2[1], wih2[2], wih2[3]);
    float4 H2 = make_float4(whh2[0], whh2[1], whh2[2], whh2[3]);
    float4 B2 = make_float4(bih2[0] + bhh2[0], bih2[1] + bhh2[1],
                            bih2[2] + bhh2[2], bih2[3] + bhh2[3]);

    float c0 = 0.f, h0 = 0.f, c1 = 0.f, h1 = 0.f, c2 = 0.f, h2v = 0.f;
    float4 p0 = g_pb0[b];
    float4 p1 = g_pb0[256 + b];

    for (int tt = 0; tt < T_ + 2; ++tt) {
        float4 pn = (tt + 2 < T_) ? g_pb0[(size_t)(tt + 2) * 256 + b]
                                  : make_float4(0.f, 0.f, 0.f, 0.f);
        float in0 = h0, in1 = h1;
        if (tt < T_) step1(p0, W0, c0, h0);
        if (tt >= 1 && tt < T_ + 1) {
            float4 pre = make_float4(fmaf(I1.x, in0, B1.x), fmaf(I1.y, in0, B1.y),
                                     fmaf(I1.z, in0, B1.z), fmaf(I1.w, in0, B1.w));
            step1(pre, H1, c1, h1);
        }
        if (tt >= 2) {
            float4 pre = make_float4(fmaf(I2.x, in1, B2.x), fmaf(I2.y, in1, B2.y),
                                     fmaf(I2.z, in1, B2.z), fmaf(I2.w, in1, B2.w));
            step1(pre, H2, c2, h2v);
            out[(size_t)b * T_ + (tt - 2)] = h2v;
        }
        p0 = p1; p1 = pn;
    }
}

// ---------------------------------------------------------------------------
extern "C" void kernel_launch(void* const* d_in, const int* in_sizes, int n_in,
                              void* d_out, int out_size)
{
    const float* x = (const float*)d_in[0];
    const float *wih_a0 = (const float*)d_in[1],  *whh_a0 = (const float*)d_in[2];
    const float *bih_a0 = (const float*)d_in[3],  *bhh_a0 = (const float*)d_in[4];
    const float *wih_a1 = (const float*)d_in[5],  *whh_a1 = (const float*)d_in[6];
    const float *bih_a1 = (const float*)d_in[7],  *bhh_a1 = (const float*)d_in[8];
    const float *wih_a2 = (const float*)d_in[9],  *whh_a2 = (const float*)d_in[10];
    const float *bih_a2 = (const float*)d_in[11], *bhh_a2 = (const float*)d_in[12];
    const float *wih_b0 = (const float*)d_in[13], *whh_b0 = (const float*)d_in[14];
    const float *bih_b0 = (const float*)d_in[15], *bhh_b0 = (const float*)d_in[16];
    const float *wih_b1 = (const float*)d_in[17], *whh_b1 = (const float*)d_in[18];
    const float *bih_b1 = (const float*)d_in[19], *bhh_b1 = (const float*)d_in[20];
    const float *wih_b2 = (const float*)d_in[21], *whh_b2 = (const float*)d_in[22];
    const float *bih_b2 = (const float*)d_in[23], *bhh_b2 = (const float*)d_in[24];
    float* out = (float*)d_out;

    cudaFuncSetAttribute(fuseA, cudaFuncAttributeMaxDynamicSharedMemorySize,
                         SMEM_FUSE_BYTES);

    // fused a0+a1+a2 pipeline -> g_seqA
    fuseA<<<NPAIR, 256, SMEM_FUSE_BYTES>>>(
        x,
        wih_a0, whh_a0, bih_a0, bhh_a0,
        wih_a1, whh_a1, bih_a1, bhh_a1,
        wih_a2, whh_a2, bih_a2, bhh_a2);
    // b0 pre-gates from g_seqA
    preb0<<<512, 256>>>(wih_b0, bih_b0, bhh_b0);
    // b0/b1/b2 fused scalar recurrences -> out
    b012<<<8, 32>>>(whh_b0, wih_b1, whh_b1, bih_b1, bhh_b1,
                    wih_b2, whh_b2, bih_b2, bhh_b2, out);
}